// round 11
// baseline (speedup 1.0000x reference)
#include <cuda_runtime.h>
#include <math.h>

#define Tn   4
#define Bn   32
#define Cn   384
#define HFn  1536
#define HWn  196
#define En   8
#define Nn   128
#define OUT_MAIN (Nn*Cn*HWn)
#define NG   32
#define GSZ  48
#define NR   12
#define FULLMASK 0xffffffffu

#define PB   28                  // pixels per worker block (7 per token)
#define PBS  29                  // smem row stride (odd -> bank-conflict-free)
#define TPB  224                 // 7 warps; each warp owns 4 pixels
#define XS_ELEMS (Cn*PBS)
#define COMB_OFF XS_ELEMS        // comb[384]
#define GATE_OFF (COMB_OFF+Cn)   // e0,e1,gw0,gw1
#define MSK_OFF  (GATE_OFF+4)    // [7][NR] unsigned
#define SM_FLOATS (MSK_OFF + 7*NR)
#define SM_BYTES  (SM_FLOATS*4)

// ---------------- device scratch ----------------
__device__ float    g_w1t[En*Cn*HFn];      // [e][c][o] transposed w1 (coalesced tier-3)
__device__ float    g_colmax32[En*Cn*NG];  // [e][c][g]
__device__ float    g_thrmin32[En*NG];
__device__ float    g_thrall[En];
__device__ unsigned g_maxcm_u[En];         // zero-init; monotone-key atomicMax (idempotent)
__device__ float    g_xmin[En];            // exact: x >= xmin  <=>  (x/tau - 1) >= 0
__device__ float    g_m2c[En*Cn];
__device__ float    g_a2c[En*Cn];
__device__ float    g_sbar[Nn*Cn];

__device__ __forceinline__ unsigned fkey(float f){
  unsigned b = __float_as_uint(f);
  return (b & 0x80000000u) ? ~b : (b | 0x80000000u);
}
__device__ __forceinline__ float funkey(unsigned k){
  unsigned b = (k & 0x80000000u) ? (k & 0x7fffffffu) : ~k;
  return __uint_as_float(b);
}

// ============ kernel 1: heterogeneous prep (transpose+colmax | thresholds | LIF) ============
__global__ void __launch_bounds__(256) k_prepall(
    const float* __restrict__ x,  const float* __restrict__ w1,
    const float* __restrict__ g1, const float* __restrict__ be1,
    const float* __restrict__ m1, const float* __restrict__ v1,
    const float* __restrict__ b1,
    const float* __restrict__ g2, const float* __restrict__ be2,
    const float* __restrict__ m2, const float* __restrict__ v2,
    const float* __restrict__ b2,
    const float* __restrict__ taus){
  int b = blockIdx.x;
  int tid = threadIdx.x, lane = tid & 31;

  if (b < 256){
    // ---- transpose + colmax role: block = (e,g) handles w1 rows [g*48,(g+1)*48) ----
    __shared__ float tile[GSZ][129];
    int e = b >> 5, g = b & 31;
    float lmax = -1e30f;
    #pragma unroll
    for (int ch=0; ch<3; ch++){
      int c0 = ch*128;
      // coalesced load 48x128
      for (int i=tid; i<GSZ*128; i+=256){
        int o = i >> 7, c = i & 127;
        tile[o][c] = w1[((size_t)e*HFn + g*GSZ + o)*Cn + c0 + c];
      }
      __syncthreads();
      // transposed store (mostly-contiguous 192B runs per c)
      for (int i=tid; i<GSZ*128; i+=256){
        int c = i/GSZ, o = i - c*GSZ;
        g_w1t[((size_t)e*Cn + c0 + c)*HFn + g*GSZ + o] = tile[o][c];
      }
      // colmax for these 128 channels
      if (tid < 128){
        float m = -1e30f;
        #pragma unroll 8
        for (int o=0;o<GSZ;o++) m = fmaxf(m, tile[o][tid]);
        g_colmax32[((size_t)e*Cn + c0 + tid)*NG + g] = m;
        lmax = fmaxf(lmax, m);
      }
      __syncthreads();
    }
    #pragma unroll
    for (int d=16;d>=1;d>>=1) lmax = fmaxf(lmax, __shfl_xor_sync(FULLMASK, lmax, d));
    if (lane==0 && tid < 128) atomicMax(&g_maxcm_u[e], fkey(lmax));
    return;
  }

  if (b < 264){
    int e = b - 256;
    __shared__ float s_thr[HFn];
    float tau = taus[e];
    for (int o = tid; o < HFn; o += 256){
      float iv = g1[e*HFn+o] * rsqrtf(v1[e*HFn+o] + 1e-5f);
      float sh = be1[e*HFn+o] - m1[e*HFn+o]*iv;
      s_thr[o] = (iv > 0.0f) ? ((tau - sh)/iv - b1[e*HFn+o]) : -1e30f;
    }
    for (int c = tid; c < Cn; c += 256){
      float inv = g2[e*Cn+c] * rsqrtf(v2[e*Cn+c] + 1e-5f);
      float sh  = be2[e*Cn+c] - m2[e*Cn+c]*inv;
      g_m2c[e*Cn+c] = inv;
      g_a2c[e*Cn+c] = inv*b2[e*Cn+c] + sh;
    }
    __syncthreads();
    if (tid < NG){
      float mn = 1e30f;
      #pragma unroll 8
      for (int i=0;i<GSZ;i++) mn = fminf(mn, s_thr[tid*GSZ + i]);
      g_thrmin32[e*NG + tid] = mn;
      float ta = mn;
      #pragma unroll
      for (int d=16;d>=1;d>>=1) ta = fminf(ta, __shfl_xor_sync(FULLMASK, ta, d));
      if (tid==0) g_thrall[e] = ta;
    }
    if (tid==64){
      float y = tau;                       // tau/tau == 1 exactly
      for (int it=0; it<8; it++){
        float z = nextafterf(y, 0.0f);
        if ((z/tau - 1.0f) >= 0.0f) y = z; else break;
      }
      g_xmin[e] = y;
    }
    return;
  }

  {
    int w = (b - 264)*8 + (tid >> 5);      // 0..12287 = bidx*Cn + c
    int bi = w / Cn, c = w - bi*Cn;
    const float* xb = x + ((size_t)bi*Cn + c)*HWn;
    float v[7] = {0.f,0.f,0.f,0.f,0.f,0.f,0.f};
    #pragma unroll
    for (int t=0;t<Tn;t++){
      const float* xt = xb + (size_t)t*Bn*Cn*HWn;
      int cntl = 0;
      #pragma unroll
      for (int k=0;k<7;k++){
        int p = lane + k*32;
        if (p < HWn){
          float xv = xt[p];
          v[k] += (xv - v[k])*0.5f;
          bool s = (v[k] - 1.0f) >= 0.0f;
          cntl += s ? 1 : 0;
          if (s) v[k] = 0.0f;
        }
      }
      int cnt = __reduce_add_sync(FULLMASK, cntl);
      if (lane==0) g_sbar[(t*Bn+bi)*Cn + c] = (float)cnt / (float)HWn;
    }
  }
}

// ---------------- inline gate (identical for workers and aux) ----------------
__device__ __forceinline__ void gate_compute(
    int n, int lane,
    const float* __restrict__ rw, const float* __restrict__ rb,
    const float* __restrict__ rg, const float* __restrict__ rbeta,
    const float* __restrict__ rmean, const float* __restrict__ rvar,
    int& i1o, int& i2o, float& g1o, float& g2o, float* probs){
  float sv[NR];
  #pragma unroll
  for (int r=0;r<NR;r++) sv[r] = g_sbar[n*Cn + r*32 + lane];
  float lg[En];
  #pragma unroll
  for (int e=0;e<En;e++){
    float v = 0.0f;
    #pragma unroll
    for (int r=0;r<NR;r++) v += sv[r] * rw[e*Cn + r*32 + lane];
    #pragma unroll
    for (int d=16;d>=1;d>>=1) v += __shfl_xor_sync(FULLMASK, v, d);
    float inv = rg[e] * rsqrtf(rvar[e] + 1e-5f);
    lg[e] = inv*(v + rb[e]) + (rbeta[e] - rmean[e]*inv);
  }
  float mx = lg[0];
  #pragma unroll
  for (int e=1;e<En;e++) mx = fmaxf(mx, lg[e]);
  float pe[En]; float sum = 0.0f;
  #pragma unroll
  for (int e=0;e<En;e++){ pe[e] = expf(lg[e]-mx); sum += pe[e]; }
  #pragma unroll
  for (int e=0;e<En;e++) pe[e] /= sum;
  int i1 = 0; float p1 = pe[0];
  #pragma unroll
  for (int e=1;e<En;e++) if (pe[e] > p1){ p1 = pe[e]; i1 = e; }
  int i2 = -1; float p2 = -1.0f;
  #pragma unroll
  for (int e=0;e<En;e++) if (e != i1 && pe[e] > p2){ p2 = pe[e]; i2 = e; }
  float ws = p1 + p2;
  i1o = i1; i2o = i2; g1o = p1/ws; g2o = p2/ws;
  if (probs){
    #pragma unroll
    for (int e=0;e<En;e++) probs[e] = pe[e];
  }
}

// ============ kernel 2: expert (smem-staged, warp-specialized prologue) ============
extern __shared__ float xs[];

__global__ void __launch_bounds__(TPB, 4) k_expert(
    const float* __restrict__ x,
    const float* __restrict__ rw, const float* __restrict__ rb,
    const float* __restrict__ rg, const float* __restrict__ rbeta,
    const float* __restrict__ rmean, const float* __restrict__ rvar,
    const float* __restrict__ taus,
    const float* __restrict__ b1,
    const float* __restrict__ g1, const float* __restrict__ be1,
    const float* __restrict__ m1, const float* __restrict__ v1,
    const float* __restrict__ w2,
    float* __restrict__ out, float* __restrict__ auxout){
  int b = blockIdx.x;
  int tid = threadIdx.x, lane = tid & 31, w = tid >> 5;

  if (b == 0){
    // ---- aux block (wave 1, overlapped with workers) ----
    float* fs = xs;        // [7][8]
    float* ps = xs + 64;   // [7][8]
    float facc[En], pacc[En];
    #pragma unroll
    for (int e=0;e<En;e++){ facc[e]=0.f; pacc[e]=0.f; }
    for (int n = w; n < Nn; n += 7){
      int i1,i2; float a,bb; float pe[En];
      gate_compute(n, lane, rw, rb, rg, rbeta, rmean, rvar, i1, i2, a, bb, pe);
      #pragma unroll
      for (int e=0;e<En;e++){
        facc[e] += (i1==e || i2==e) ? 1.0f : 0.0f;
        pacc[e] += pe[e];
      }
    }
    if (lane==0){
      #pragma unroll
      for (int e=0;e<En;e++){ fs[w*8+e] = facc[e]; ps[w*8+e] = pacc[e]; }
    }
    __syncthreads();
    if (tid==0 && auxout){
      float s = 0.0f;
      #pragma unroll
      for (int e=0;e<En;e++){
        float fe = 0.f, pp = 0.f;
        #pragma unroll
        for (int q=0;q<7;q++){ fe += fs[q*8+e]; pp += ps[q*8+e]; }
        s += (fe/(float)Nn) * (pp/(float)Nn);
      }
      auxout[0] = 0.01f * (float)En * s;
    }
    return;
  }

  int wb = b - 1;
  int n = wb / 7;
  int pbase = (wb - n*7) * PB;
  float* comb = xs + COMB_OFF;
  float* gsh  = xs + GATE_OFF;
  unsigned* msks = (unsigned*)(xs + MSK_OFF) + w*NR;
  const float* xrow = x + (size_t)n*Cn*HWn + pbase;

  // ---- warp-specialized prologue: warp 0 gate+comb ; warps 1-6 tile load ----
  if (w == 0){
    int e0_, e1_; float gw0_, gw1_;
    gate_compute(n, lane, rw, rb, rg, rbeta, rmean, rvar, e0_, e1_, gw0_, gw1_, (float*)0);
    if (lane == 0){
      gsh[0] = __int_as_float(e0_); gsh[1] = __int_as_float(e1_);
      gsh[2] = gw0_; gsh[3] = gw1_;
    }
    // comb[c] = gw0*a2[e0][c] + gw1*a2[e1][c]
    #pragma unroll
    for (int r=0;r<NR;r++){
      int c = r*32 + lane;
      comb[c] = gw0_*g_a2c[e0_*Cn+c] + gw1_*g_a2c[e1_*Cn+c];
    }
  } else {
    // 6 warps load 384 rows; lanes 0-27 each load one pixel of the row
    for (int c = w-1; c < Cn; c += 6){
      if (lane < PB) xs[c*PBS + lane] = xrow[(size_t)c*HWn + lane];
    }
  }
  __syncthreads();

  int   e0  = __float_as_int(gsh[0]), e1 = __float_as_int(gsh[1]);
  float gw0 = gsh[2], gw1 = gsh[3];
  float gws  = gw0 + gw1;
  float xm0  = g_xmin[e0], xm1 = g_xmin[e1];
  float thr0 = g_thrall[e0] - 1e-3f, thr1 = g_thrall[e1] - 1e-3f;
  float mc0  = funkey(g_maxcm_u[e0]), mc1 = funkey(g_maxcm_u[e1]);
  float tau0 = taus[e0], tau1 = taus[e1];

  // ---- compute: warp w owns smem columns 4w..4w+3; no block barriers here ----
  for (int j=0;j<4;j++){
    int col = w*4 + j;
    float xv[NR];
    #pragma unroll
    for (int r=0;r<NR;r++) xv[r] = xs[(r*32+lane)*PBS + col];

    unsigned lmA = 0, lmB = 0;
    #pragma unroll
    for (int r=0;r<NR;r++){
      lmA |= (xv[r] >= xm0) ? (1u << r) : 0u;
      lmB |= (xv[r] >= xm1) ? (1u << r) : 0u;
    }
    #pragma unroll
    for (int r=0;r<NR;r++) xv[r] = fmaf(xv[r], gws, comb[r*32+lane]);

    int pk = __popc(lmA) | (__popc(lmB) << 16);
    int sums = __reduce_add_sync(FULLMASK, pk);
    int cntA = sums & 0xffff, cntB = sums >> 16;

    bool lightA = (float)cntA * mc0 < thr0;
    bool lightB = (float)cntB * mc1 < thr1;
    if (!(lightA && lightB)){
      #pragma unroll
      for (int k=0;k<2;k++){
        if (k ? lightB : lightA) continue;
        int   e   = k ? e1   : e0;
        float gw  = k ? gw1  : gw0;
        float tau = k ? tau1 : tau0;
        unsigned lm = k ? lmB : lmA;

        #pragma unroll
        for (int r=0;r<NR;r++){
          unsigned m = __ballot_sync(FULLMASK, (lm >> r) & 1u);
          if (lane == 0) msks[r] = m;
        }
        __syncwarp();

        // tier 2: per-group bound; lane = group g (coalesced colmax rows)
        float ub;
        {
          const float* cmB = g_colmax32 + (size_t)e*Cn*NG + lane;
          float pr[4] = {0.f,0.f,0.f,0.f};
          #pragma unroll
          for (int r=0;r<NR;r++){
            unsigned mm = msks[r];
            float pp = 0.0f;
            while (mm){
              int bb = __ffs(mm)-1; mm &= mm-1;
              pp += cmB[(size_t)(r*32 + bb)*NG];
            }
            pr[r & 3] += pp;
          }
          ub = (pr[0]+pr[1]) + (pr[2]+pr[3]);
        }
        bool fail = ub >= g_thrmin32[e*NG + lane] - 1e-3f;
        unsigned fm = __ballot_sync(FULLMASK, fail);
        if (fm == 0) continue;

        // tier 3: exact for failing groups — COALESCED via g_w1t rows
        float a[NR];
        #pragma unroll
        for (int r=0;r<NR;r++) a[r] = 0.0f;
        int nf = 0;
        const float* w1c = g_w1t + (size_t)e*Cn*HFn;
        while (fm){
          int g = __ffs(fm)-1; fm &= fm-1;
          int obase = g*GSZ;
          float h0 = 0.0f, h1 = 0.0f;
          #pragma unroll
          for (int r=0;r<NR;r++){
            unsigned mm = msks[r];
            while (mm){
              int bb = __ffs(mm)-1; mm &= mm-1;
              const float* row = w1c + (size_t)(r*32 + bb)*HFn + obase;
              h0 += row[lane];                    // 128B contiguous
              if (lane < 16) h1 += row[32+lane];  // next 64B
            }
          }
          int o0 = obase + lane;
          float iv0 = g1[e*HFn+o0] * rsqrtf(v1[e*HFn+o0] + 1e-5f);
          float q0  = iv0*b1[e*HFn+o0] + (be1[e*HFn+o0] - m1[e*HFn+o0]*iv0) - tau;
          bool f0 = fmaf(iv0, h0, q0) >= 0.0f;
          bool f1 = false;
          if (lane < 16){
            int o1 = obase + 32 + lane;
            float iv1 = g1[e*HFn+o1] * rsqrtf(v1[e*HFn+o1] + 1e-5f);
            float q1  = iv1*b1[e*HFn+o1] + (be1[e*HFn+o1] - m1[e*HFn+o1]*iv1) - tau;
            f1 = fmaf(iv1, h1, q1) >= 0.0f;
          }
          unsigned fa0 = __ballot_sync(FULLMASK, f0);
          unsigned fa1 = __ballot_sync(FULLMASK, f1);
          unsigned t = fa0;
          while (t){
            int bb = __ffs(t)-1; t &= t-1;
            const float* w2b = w2 + ((size_t)e*Cn + lane)*HFn + (obase + bb);
            #pragma unroll
            for (int r=0;r<NR;r++) a[r] += w2b[(size_t)r*32*HFn];
            nf++;
          }
          t = fa1;
          while (t){
            int bb = __ffs(t)-1; t &= t-1;
            const float* w2b = w2 + ((size_t)e*Cn + lane)*HFn + (obase + 32 + bb);
            #pragma unroll
            for (int r=0;r<NR;r++) a[r] += w2b[(size_t)r*32*HFn];
            nf++;
          }
        }
        if (nf){
          #pragma unroll
          for (int r=0;r<NR;r++){
            float inv2 = g_m2c[e*Cn + r*32 + lane];
            xv[r] += gw * (inv2 * a[r]);
          }
        }
      }
    }

    #pragma unroll
    for (int r=0;r<NR;r++) xs[(r*32+lane)*PBS + col] = xv[r];
  }

  __syncthreads();

  // ---- cooperative warp-per-row store ----
  float* orow = out + (size_t)n*Cn*HWn + pbase;
  for (int c = w; c < Cn; c += 7){
    if (lane < PB) orow[(size_t)c*HWn + lane] = xs[c*PBS + lane];
  }
}

// ---------------- launch ----------------
extern "C" void kernel_launch(void* const* d_in, const int* in_sizes, int n_in,
                              void* d_out, int out_size){
  const float* x      = (const float*)d_in[0];
  const float* rw     = (const float*)d_in[1];
  const float* rb     = (const float*)d_in[2];
  const float* rgam   = (const float*)d_in[3];
  const float* rbeta  = (const float*)d_in[4];
  const float* rmean  = (const float*)d_in[5];
  const float* rvar   = (const float*)d_in[6];
  const float* w1     = (const float*)d_in[7];
  const float* b1     = (const float*)d_in[8];
  const float* g1     = (const float*)d_in[9];
  const float* be1    = (const float*)d_in[10];
  const float* m1     = (const float*)d_in[11];
  const float* v1     = (const float*)d_in[12];
  const float* w2     = (const float*)d_in[13];
  const float* b2     = (const float*)d_in[14];
  const float* g2     = (const float*)d_in[15];
  const float* be2    = (const float*)d_in[16];
  const float* m2     = (const float*)d_in[17];
  const float* v2     = (const float*)d_in[18];
  const float* taus   = (const float*)d_in[19];
  float* out = (float*)d_out;
  (void)in_sizes; (void)n_in;

  cudaFuncSetAttribute(k_expert, cudaFuncAttributeMaxDynamicSharedMemorySize, SM_BYTES);

  k_prepall<<<264 + (Bn*Cn)/8, 256>>>(x, w1, g1, be1, m1, v1, b1,
                                      g2, be2, m2, v2, b2, taus);
  float* auxp = (out_size > OUT_MAIN) ? (out + OUT_MAIN) : nullptr;
  k_expert<<<1 + Nn*7, TPB, SM_BYTES>>>(x, rw, rb, rgam, rbeta, rmean, rvar,
                                        taus, b1, g1, be1, m1, v1, w2,
                                        out, auxp);
}

// round 12
// speedup vs baseline: 1.1788x; 1.1788x over previous
#include <cuda_runtime.h>
#include <math.h>

#define Tn   4
#define Bn   32
#define Cn   384
#define HFn  1536
#define HWn  196
#define En   8
#define Nn   128
#define OUT_MAIN (Nn*Cn*HWn)
#define NG   32
#define GSZ  48
#define NR   12
#define FULLMASK 0xffffffffu

#define PB   28                  // pixels per work item (7 per token)
#define PBS  29                  // smem row stride (odd -> bank-conflict-free)
#define TPB  224                 // 7 warps; each warp owns 4 pixels
#define NWORK (Nn*7)             // 896 work items
#define XS_ELEMS (Cn*PBS)
#define COMB_OFF XS_ELEMS        // comb[384]
#define GATE_OFF (COMB_OFF+Cn)   // e0,e1,gw0,gw1
#define MSK_OFF  (GATE_OFF+4)    // [7][NR] unsigned
#define TKT_OFF  (MSK_OFF+7*NR)  // shared ticket slot
#define SM_FLOATS (TKT_OFF + 1)
#define SM_BYTES  (SM_FLOATS*4)

// ---------------- device scratch ----------------
__device__ float    g_colmax32[En*Cn*NG];  // [e][c][g]
__device__ float    g_thrmin32[En*NG];
__device__ float    g_thrall[En];
__device__ unsigned g_maxcm_u[En];         // zero-init; monotone-key atomicMax (idempotent)
__device__ float    g_xmin[En];            // exact: x >= xmin  <=>  (x/tau - 1) >= 0
__device__ float    g_m2c[En*Cn];
__device__ float    g_a2c[En*Cn];
__device__ float    g_sbar[Nn*Cn];
__device__ int      g_ticket;              // reset by k_prepall each launch

__device__ __forceinline__ unsigned fkey(float f){
  unsigned b = __float_as_uint(f);
  return (b & 0x80000000u) ? ~b : (b | 0x80000000u);
}
__device__ __forceinline__ float funkey(unsigned k){
  unsigned b = (k & 0x80000000u) ? (k & 0x7fffffffu) : ~k;
  return __uint_as_float(b);
}

// ============ kernel 1: heterogeneous prep (colmax | thresholds | LIF) ============
__global__ void __launch_bounds__(256) k_prepall(
    const float* __restrict__ x,  const float* __restrict__ w1,
    const float* __restrict__ g1, const float* __restrict__ be1,
    const float* __restrict__ m1, const float* __restrict__ v1,
    const float* __restrict__ b1,
    const float* __restrict__ g2, const float* __restrict__ be2,
    const float* __restrict__ m2, const float* __restrict__ v2,
    const float* __restrict__ b2,
    const float* __restrict__ taus){
  int b = blockIdx.x;
  int tid = threadIdx.x, lane = tid & 31;

  if (b < 256){
    if (b == 0 && tid == 0) g_ticket = 0;      // stream-ordered reset for k_expert
    int e = b >> 5, g = b & 31;
    float lmax = -1e30f;
    for (int c = tid; c < Cn; c += 256){
      const float* base = w1 + ((size_t)e*HFn + g*GSZ)*Cn + c;
      float m = -1e30f;
      #pragma unroll 8
      for (int o=0;o<GSZ;o++) m = fmaxf(m, base[(size_t)o*Cn]);
      g_colmax32[((size_t)e*Cn + c)*NG + g] = m;
      lmax = fmaxf(lmax, m);
    }
    #pragma unroll
    for (int d=16;d>=1;d>>=1) lmax = fmaxf(lmax, __shfl_xor_sync(FULLMASK, lmax, d));
    if (lane==0) atomicMax(&g_maxcm_u[e], fkey(lmax));
    return;
  }

  if (b < 264){
    int e = b - 256;
    __shared__ float s_thr[HFn];
    float tau = taus[e];
    for (int o = tid; o < HFn; o += 256){
      float iv = g1[e*HFn+o] * rsqrtf(v1[e*HFn+o] + 1e-5f);
      float sh = be1[e*HFn+o] - m1[e*HFn+o]*iv;
      s_thr[o] = (iv > 0.0f) ? ((tau - sh)/iv - b1[e*HFn+o]) : -1e30f;
    }
    for (int c = tid; c < Cn; c += 256){
      float inv = g2[e*Cn+c] * rsqrtf(v2[e*Cn+c] + 1e-5f);
      float sh  = be2[e*Cn+c] - m2[e*Cn+c]*inv;
      g_m2c[e*Cn+c] = inv;
      g_a2c[e*Cn+c] = inv*b2[e*Cn+c] + sh;
    }
    __syncthreads();
    if (tid < NG){
      float mn = 1e30f;
      #pragma unroll 8
      for (int i=0;i<GSZ;i++) mn = fminf(mn, s_thr[tid*GSZ + i]);
      g_thrmin32[e*NG + tid] = mn;
      float ta = mn;
      #pragma unroll
      for (int d=16;d>=1;d>>=1) ta = fminf(ta, __shfl_xor_sync(FULLMASK, ta, d));
      if (tid==0) g_thrall[e] = ta;
    }
    if (tid==64){
      float y = tau;                       // tau/tau == 1 exactly
      for (int it=0; it<8; it++){
        float z = nextafterf(y, 0.0f);
        if ((z/tau - 1.0f) >= 0.0f) y = z; else break;
      }
      g_xmin[e] = y;
    }
    return;
  }

  {
    int w = (b - 264)*8 + (tid >> 5);      // 0..12287 = bidx*Cn + c
    int bi = w / Cn, c = w - bi*Cn;
    const float* xb = x + ((size_t)bi*Cn + c)*HWn;
    float v[7] = {0.f,0.f,0.f,0.f,0.f,0.f,0.f};
    #pragma unroll
    for (int t=0;t<Tn;t++){
      const float* xt = xb + (size_t)t*Bn*Cn*HWn;
      int cntl = 0;
      #pragma unroll
      for (int k=0;k<7;k++){
        int p = lane + k*32;
        if (p < HWn){
          float xv = xt[p];
          v[k] += (xv - v[k])*0.5f;
          bool s = (v[k] - 1.0f) >= 0.0f;
          cntl += s ? 1 : 0;
          if (s) v[k] = 0.0f;
        }
      }
      int cnt = __reduce_add_sync(FULLMASK, cntl);
      if (lane==0) g_sbar[(t*Bn+bi)*Cn + c] = (float)cnt / (float)HWn;
    }
  }
}

// ---------------- inline gate (identical for workers and aux) ----------------
__device__ __forceinline__ void gate_compute(
    int n, int lane,
    const float* __restrict__ rw, const float* __restrict__ rb,
    const float* __restrict__ rg, const float* __restrict__ rbeta,
    const float* __restrict__ rmean, const float* __restrict__ rvar,
    int& i1o, int& i2o, float& g1o, float& g2o, float* probs){
  float sv[NR];
  #pragma unroll
  for (int r=0;r<NR;r++) sv[r] = g_sbar[n*Cn + r*32 + lane];
  float lg[En];
  #pragma unroll
  for (int e=0;e<En;e++){
    float v = 0.0f;
    #pragma unroll
    for (int r=0;r<NR;r++) v += sv[r] * rw[e*Cn + r*32 + lane];
    #pragma unroll
    for (int d=16;d>=1;d>>=1) v += __shfl_xor_sync(FULLMASK, v, d);
    float inv = rg[e] * rsqrtf(rvar[e] + 1e-5f);
    lg[e] = inv*(v + rb[e]) + (rbeta[e] - rmean[e]*inv);
  }
  float mx = lg[0];
  #pragma unroll
  for (int e=1;e<En;e++) mx = fmaxf(mx, lg[e]);
  float pe[En]; float sum = 0.0f;
  #pragma unroll
  for (int e=0;e<En;e++){ pe[e] = expf(lg[e]-mx); sum += pe[e]; }
  #pragma unroll
  for (int e=0;e<En;e++) pe[e] /= sum;
  int i1 = 0; float p1 = pe[0];
  #pragma unroll
  for (int e=1;e<En;e++) if (pe[e] > p1){ p1 = pe[e]; i1 = e; }
  int i2 = -1; float p2 = -1.0f;
  #pragma unroll
  for (int e=0;e<En;e++) if (e != i1 && pe[e] > p2){ p2 = pe[e]; i2 = e; }
  float ws = p1 + p2;
  i1o = i1; i2o = i2; g1o = p1/ws; g2o = p2/ws;
  if (probs){
    #pragma unroll
    for (int e=0;e<En;e++) probs[e] = pe[e];
  }
}

// ============ kernel 2: persistent expert workers + aux as block 0 ============
extern __shared__ float xs[];

__global__ void __launch_bounds__(TPB, 4) k_expert(
    const float* __restrict__ x,
    const float* __restrict__ rw, const float* __restrict__ rb,
    const float* __restrict__ rg, const float* __restrict__ rbeta,
    const float* __restrict__ rmean, const float* __restrict__ rvar,
    const float* __restrict__ taus,
    const float* __restrict__ w1, const float* __restrict__ b1,
    const float* __restrict__ g1, const float* __restrict__ be1,
    const float* __restrict__ m1, const float* __restrict__ v1,
    const float* __restrict__ w2,
    float* __restrict__ out, float* __restrict__ auxout){
  int b = blockIdx.x;
  int tid = threadIdx.x, lane = tid & 31, w = tid >> 5;

  if (b == 0){
    // ---- aux block (wave 1, overlapped with workers) ----
    float* fs = xs;        // [7][8]
    float* ps = xs + 64;   // [7][8]
    float facc[En], pacc[En];
    #pragma unroll
    for (int e=0;e<En;e++){ facc[e]=0.f; pacc[e]=0.f; }
    for (int n = w; n < Nn; n += 7){
      int i1,i2; float a,bb; float pe[En];
      gate_compute(n, lane, rw, rb, rg, rbeta, rmean, rvar, i1, i2, a, bb, pe);
      #pragma unroll
      for (int e=0;e<En;e++){
        facc[e] += (i1==e || i2==e) ? 1.0f : 0.0f;
        pacc[e] += pe[e];
      }
    }
    if (lane==0){
      #pragma unroll
      for (int e=0;e<En;e++){ fs[w*8+e] = facc[e]; ps[w*8+e] = pacc[e]; }
    }
    __syncthreads();
    if (tid==0 && auxout){
      float s = 0.0f;
      #pragma unroll
      for (int e=0;e<En;e++){
        float fe = 0.f, pp = 0.f;
        #pragma unroll
        for (int q=0;q<7;q++){ fe += fs[q*8+e]; pp += ps[q*8+e]; }
        s += (fe/(float)Nn) * (pp/(float)Nn);
      }
      auxout[0] = 0.01f * (float)En * s;
    }
    return;
  }

  float* comb = xs + COMB_OFF;
  float* gsh  = xs + GATE_OFF;
  unsigned* msks = (unsigned*)(xs + MSK_OFF) + w*NR;
  int* tkt = (int*)(xs + TKT_OFF);

  for (;;){
    // ---- pull next work item (dynamic load balance; no wave quantization) ----
    if (tid == 0) *tkt = atomicAdd(&g_ticket, 1);
    __syncthreads();
    int wb = *tkt;
    if (wb >= NWORK) break;

    int n = wb / 7;
    int pbase = (wb - n*7) * PB;
    const float* xrow = x + (size_t)n*Cn*HWn + pbase;

    // ---- cooperative coalesced load of the x tile [384][28] (stride 29) ----
    for (int i = tid; i < Cn*PB; i += TPB){
      int c = i / PB, p = i - c*PB;
      xs[c*PBS + p] = xrow[(size_t)c*HWn + p];
    }

    // ---- gate once per block (warp 0), overlapped with in-flight tile loads ----
    if (w == 0){
      int e0_, e1_; float gw0_, gw1_;
      gate_compute(n, lane, rw, rb, rg, rbeta, rmean, rvar, e0_, e1_, gw0_, gw1_, (float*)0);
      if (lane == 0){
        gsh[0] = __int_as_float(e0_); gsh[1] = __int_as_float(e1_);
        gsh[2] = gw0_; gsh[3] = gw1_;
      }
    }
    __syncthreads();

    int   e0  = __float_as_int(gsh[0]), e1 = __float_as_int(gsh[1]);
    float gw0 = gsh[2], gw1 = gsh[3];

    // ---- comb[c] = gw0*a2[e0][c] + gw1*a2[e1][c] ----
    for (int c = tid; c < Cn; c += TPB)
      comb[c] = gw0*g_a2c[e0*Cn+c] + gw1*g_a2c[e1*Cn+c];

    float gws  = gw0 + gw1;
    float xm0  = g_xmin[e0], xm1 = g_xmin[e1];
    float thr0 = g_thrall[e0] - 1e-3f, thr1 = g_thrall[e1] - 1e-3f;
    float mc0  = funkey(g_maxcm_u[e0]), mc1 = funkey(g_maxcm_u[e1]);
    float tau0 = taus[e0], tau1 = taus[e1];

    __syncthreads();

    // ---- compute: warp w owns smem columns 4w..4w+3; no block barriers here ----
    for (int j=0;j<4;j++){
      int col = w*4 + j;
      float xv[NR];
      #pragma unroll
      for (int r=0;r<NR;r++) xv[r] = xs[(r*32+lane)*PBS + col];

      unsigned lmA = 0, lmB = 0;
      #pragma unroll
      for (int r=0;r<NR;r++){
        lmA |= (xv[r] >= xm0) ? (1u << r) : 0u;
        lmB |= (xv[r] >= xm1) ? (1u << r) : 0u;
      }
      #pragma unroll
      for (int r=0;r<NR;r++) xv[r] = fmaf(xv[r], gws, comb[r*32+lane]);

      int pk = __popc(lmA) | (__popc(lmB) << 16);
      int sums = __reduce_add_sync(FULLMASK, pk);
      int cntA = sums & 0xffff, cntB = sums >> 16;

      bool lightA = (float)cntA * mc0 < thr0;
      bool lightB = (float)cntB * mc1 < thr1;
      if (!(lightA && lightB)){
        #pragma unroll
        for (int k=0;k<2;k++){
          if (k ? lightB : lightA) continue;
          int   e   = k ? e1   : e0;
          float gw  = k ? gw1  : gw0;
          float tau = k ? tau1 : tau0;
          unsigned lm = k ? lmB : lmA;

          #pragma unroll
          for (int r=0;r<NR;r++){
            unsigned m = __ballot_sync(FULLMASK, (lm >> r) & 1u);
            if (lane == 0) msks[r] = m;
          }
          __syncwarp();

          // tier 2: per-group bound; lane = group g
          float ub;
          {
            const float* cmB = g_colmax32 + (size_t)e*Cn*NG + lane;
            float pr[4] = {0.f,0.f,0.f,0.f};
            #pragma unroll
            for (int r=0;r<NR;r++){
              unsigned mm = msks[r];
              float pp = 0.0f;
              while (mm){
                int bb = __ffs(mm)-1; mm &= mm-1;
                pp += cmB[(size_t)(r*32 + bb)*NG];
              }
              pr[r & 3] += pp;
            }
            ub = (pr[0]+pr[1]) + (pr[2]+pr[3]);
          }
          bool fail = ub >= g_thrmin32[e*NG + lane] - 1e-3f;
          unsigned fm = __ballot_sync(FULLMASK, fail);
          if (fm == 0) continue;

          // tier 3: exact for failing groups (rare)
          float a[NR];
          #pragma unroll
          for (int r=0;r<NR;r++) a[r] = 0.0f;
          int nf = 0;
          while (fm){
            int g = __ffs(fm)-1; fm &= fm-1;
            float h0 = 0.0f, h1 = 0.0f;
            const float* w1b  = w1 + ((size_t)e*HFn + g*GSZ)*Cn;
            const float* w1r0 = w1b + (size_t)lane*Cn;
            const float* w1r1 = w1b + (size_t)(32+lane)*Cn;
            #pragma unroll
            for (int r=0;r<NR;r++){
              unsigned mm = msks[r];
              while (mm){
                int bb = __ffs(mm)-1; mm &= mm-1;
                int c = r*32 + bb;
                h0 += w1r0[c];
                if (lane < 16) h1 += w1r1[c];
              }
            }
            int o0 = g*GSZ + lane;
            float iv0 = g1[e*HFn+o0] * rsqrtf(v1[e*HFn+o0] + 1e-5f);
            float q0  = iv0*b1[e*HFn+o0] + (be1[e*HFn+o0] - m1[e*HFn+o0]*iv0) - tau;
            bool f0 = fmaf(iv0, h0, q0) >= 0.0f;
            bool f1 = false;
            if (lane < 16){
              int o1 = g*GSZ + 32 + lane;
              float iv1 = g1[e*HFn+o1] * rsqrtf(v1[e*HFn+o1] + 1e-5f);
              float q1  = iv1*b1[e*HFn+o1] + (be1[e*HFn+o1] - m1[e*HFn+o1]*iv1) - tau;
              f1 = fmaf(iv1, h1, q1) >= 0.0f;
            }
            unsigned fa0 = __ballot_sync(FULLMASK, f0);
            unsigned fa1 = __ballot_sync(FULLMASK, f1);
            unsigned t = fa0;
            while (t){
              int bb = __ffs(t)-1; t &= t-1;
              const float* w2b = w2 + ((size_t)e*Cn + lane)*HFn + (g*GSZ + bb);
              #pragma unroll
              for (int r=0;r<NR;r++) a[r] += w2b[(size_t)r*32*HFn];
              nf++;
            }
            t = fa1;
            while (t){
              int bb = __ffs(t)-1; t &= t-1;
              const float* w2b = w2 + ((size_t)e*Cn + lane)*HFn + (g*GSZ + 32 + bb);
              #pragma unroll
              for (int r=0;r<NR;r++) a[r] += w2b[(size_t)r*32*HFn];
              nf++;
            }
          }
          if (nf){
            #pragma unroll
            for (int r=0;r<NR;r++){
              float inv2 = g_m2c[e*Cn + r*32 + lane];
              xv[r] += gw * (inv2 * a[r]);
            }
          }
        }
      }

      #pragma unroll
      for (int r=0;r<NR;r++) xs[(r*32+lane)*PBS + col] = xv[r];
    }

    __syncthreads();

    // ---- cooperative coalesced store ----
    float* orow = out + (size_t)n*Cn*HWn + pbase;
    for (int i = tid; i < Cn*PB; i += TPB){
      int c = i / PB, p = i - c*PB;
      orow[(size_t)c*HWn + p] = xs[c*PBS + p];
    }
    __syncthreads();   // smem (tile/gsh/comb) reused next iteration
  }
}

// ---------------- launch ----------------
extern "C" void kernel_launch(void* const* d_in, const int* in_sizes, int n_in,
                              void* d_out, int out_size){
  const float* x      = (const float*)d_in[0];
  const float* rw     = (const float*)d_in[1];
  const float* rb     = (const float*)d_in[2];
  const float* rgam   = (const float*)d_in[3];
  const float* rbeta  = (const float*)d_in[4];
  const float* rmean  = (const float*)d_in[5];
  const float* rvar   = (const float*)d_in[6];
  const float* w1     = (const float*)d_in[7];
  const float* b1     = (const float*)d_in[8];
  const float* g1     = (const float*)d_in[9];
  const float* be1    = (const float*)d_in[10];
  const float* m1     = (const float*)d_in[11];
  const float* v1     = (const float*)d_in[12];
  const float* w2     = (const float*)d_in[13];
  const float* b2     = (const float*)d_in[14];
  const float* g2     = (const float*)d_in[15];
  const float* be2    = (const float*)d_in[16];
  const float* m2     = (const float*)d_in[17];
  const float* v2     = (const float*)d_in[18];
  const float* taus   = (const float*)d_in[19];
  float* out = (float*)d_out;
  (void)in_sizes; (void)n_in;

  cudaFuncSetAttribute(k_expert, cudaFuncAttributeMaxDynamicSharedMemorySize, SM_BYTES);

  k_prepall<<<264 + (Bn*Cn)/8, 256>>>(x, w1, g1, be1, m1, v1, b1,
                                      g2, be2, m2, v2, b2, taus);
  float* auxp = (out_size > OUT_MAIN) ? (out + OUT_MAIN) : nullptr;
  // block 0 = aux; blocks 1..592 = persistent workers (4 per SM)
  k_expert<<<1 + 4*148, TPB, SM_BYTES>>>(x, rw, rb, rgam, rbeta, rmean, rvar,
                                         taus, w1, b1, g1, be1, m1, v1, w2,
                                         out, auxp);
}

// round 13
// speedup vs baseline: 1.2199x; 1.0348x over previous
#include <cuda_runtime.h>
#include <math.h>

#define Tn   4
#define Bn   32
#define Cn   384
#define HFn  1536
#define HWn  196
#define En   8
#define Nn   128
#define OUT_MAIN (Nn*Cn*HWn)
#define NG   32
#define GSZ  48
#define NR   12
#define FULLMASK 0xffffffffu

#define PB   28                  // pixels per work item (7 per token)
#define PBS  29                  // smem row stride (odd -> bank-conflict-free)
#define TPB  224                 // 7 warps; each warp owns 4 pixels
#define NWORK (Nn*7)             // 896 work items
#define XS_ELEMS (Cn*PBS)
#define COMB_OFF XS_ELEMS        // comb[384]
#define GATE_OFF (COMB_OFF+Cn)   // e0,e1,gw0,gw1
#define MSK_OFF  (GATE_OFF+4)    // [7][NR] unsigned
#define TKT_OFF  (MSK_OFF+7*NR)  // shared ticket slot
#define SM_FLOATS (TKT_OFF + 1)
#define SM_BYTES  (SM_FLOATS*4)

// ---------------- device scratch ----------------
__device__ float    g_colmax32[En*Cn*NG];  // [e][c][g]
__device__ float    g_thrmin32[En*NG];
__device__ float    g_thrall[En];
__device__ unsigned g_maxcm_u[En];         // zero-init; monotone-key atomicMax (idempotent)
__device__ float    g_xmin[En];            // exact: x >= xmin  <=>  (x/tau - 1) >= 0
__device__ float    g_m2c[En*Cn];
__device__ float    g_a2c[En*Cn];
__device__ float    g_sbar[Nn*Cn];
__device__ int      g_ticket;              // reset by k_prepall each launch

__device__ __forceinline__ unsigned fkey(float f){
  unsigned b = __float_as_uint(f);
  return (b & 0x80000000u) ? ~b : (b | 0x80000000u);
}
__device__ __forceinline__ float funkey(unsigned k){
  unsigned b = (k & 0x80000000u) ? (k & 0x7fffffffu) : ~k;
  return __uint_as_float(b);
}

// ============ kernel 1: heterogeneous prep (colmax | thresholds | LIF) ============
__global__ void __launch_bounds__(256) k_prepall(
    const float* __restrict__ x,  const float* __restrict__ w1,
    const float* __restrict__ g1, const float* __restrict__ be1,
    const float* __restrict__ m1, const float* __restrict__ v1,
    const float* __restrict__ b1,
    const float* __restrict__ g2, const float* __restrict__ be2,
    const float* __restrict__ m2, const float* __restrict__ v2,
    const float* __restrict__ b2,
    const float* __restrict__ taus){
  int b = blockIdx.x;
  int tid = threadIdx.x, lane = tid & 31;

  if (b < 256){
    if (b == 0 && tid == 0) g_ticket = 0;      // stream-ordered reset for k_expert
    int e = b >> 5, g = b & 31;
    float lmax = -1e30f;
    for (int c = tid; c < Cn; c += 256){
      const float* base = w1 + ((size_t)e*HFn + g*GSZ)*Cn + c;
      float m = -1e30f;
      #pragma unroll 8
      for (int o=0;o<GSZ;o++) m = fmaxf(m, base[(size_t)o*Cn]);
      g_colmax32[((size_t)e*Cn + c)*NG + g] = m;
      lmax = fmaxf(lmax, m);
    }
    #pragma unroll
    for (int d=16;d>=1;d>>=1) lmax = fmaxf(lmax, __shfl_xor_sync(FULLMASK, lmax, d));
    if (lane==0) atomicMax(&g_maxcm_u[e], fkey(lmax));
    return;
  }

  if (b < 264){
    int e = b - 256;
    __shared__ float s_thr[HFn];
    float tau = taus[e];
    for (int o = tid; o < HFn; o += 256){
      float iv = g1[e*HFn+o] * rsqrtf(v1[e*HFn+o] + 1e-5f);
      float sh = be1[e*HFn+o] - m1[e*HFn+o]*iv;
      s_thr[o] = (iv > 0.0f) ? ((tau - sh)/iv - b1[e*HFn+o]) : -1e30f;
    }
    for (int c = tid; c < Cn; c += 256){
      float inv = g2[e*Cn+c] * rsqrtf(v2[e*Cn+c] + 1e-5f);
      float sh  = be2[e*Cn+c] - m2[e*Cn+c]*inv;
      g_m2c[e*Cn+c] = inv;
      g_a2c[e*Cn+c] = inv*b2[e*Cn+c] + sh;
    }
    __syncthreads();
    if (tid < NG){
      float mn = 1e30f;
      #pragma unroll 8
      for (int i=0;i<GSZ;i++) mn = fminf(mn, s_thr[tid*GSZ + i]);
      g_thrmin32[e*NG + tid] = mn;
      float ta = mn;
      #pragma unroll
      for (int d=16;d>=1;d>>=1) ta = fminf(ta, __shfl_xor_sync(FULLMASK, ta, d));
      if (tid==0) g_thrall[e] = ta;
    }
    if (tid==64){
      float y = tau;                       // tau/tau == 1 exactly
      for (int it=0; it<8; it++){
        float z = nextafterf(y, 0.0f);
        if ((z/tau - 1.0f) >= 0.0f) y = z; else break;
      }
      g_xmin[e] = y;
    }
    return;
  }

  {
    int w = (b - 264)*8 + (tid >> 5);      // 0..12287 = bidx*Cn + c
    int bi = w / Cn, c = w - bi*Cn;
    const float* xb = x + ((size_t)bi*Cn + c)*HWn;
    float v[7] = {0.f,0.f,0.f,0.f,0.f,0.f,0.f};
    #pragma unroll
    for (int t=0;t<Tn;t++){
      const float* xt = xb + (size_t)t*Bn*Cn*HWn;
      int cntl = 0;
      #pragma unroll
      for (int k=0;k<7;k++){
        int p = lane + k*32;
        if (p < HWn){
          float xv = xt[p];
          v[k] += (xv - v[k])*0.5f;
          bool s = (v[k] - 1.0f) >= 0.0f;
          cntl += s ? 1 : 0;
          if (s) v[k] = 0.0f;
        }
      }
      int cnt = __reduce_add_sync(FULLMASK, cntl);
      if (lane==0) g_sbar[(t*Bn+bi)*Cn + c] = (float)cnt / (float)HWn;
    }
  }
}

// ---------------- inline gate (identical for workers and aux) ----------------
__device__ __forceinline__ void gate_compute(
    int n, int lane,
    const float* __restrict__ rw, const float* __restrict__ rb,
    const float* __restrict__ rg, const float* __restrict__ rbeta,
    const float* __restrict__ rmean, const float* __restrict__ rvar,
    int& i1o, int& i2o, float& g1o, float& g2o, float* probs){
  float sv[NR];
  #pragma unroll
  for (int r=0;r<NR;r++) sv[r] = g_sbar[n*Cn + r*32 + lane];
  float lg[En];
  #pragma unroll
  for (int e=0;e<En;e++){
    float v = 0.0f;
    #pragma unroll
    for (int r=0;r<NR;r++) v += sv[r] * rw[e*Cn + r*32 + lane];
    #pragma unroll
    for (int d=16;d>=1;d>>=1) v += __shfl_xor_sync(FULLMASK, v, d);
    float inv = rg[e] * rsqrtf(rvar[e] + 1e-5f);
    lg[e] = inv*(v + rb[e]) + (rbeta[e] - rmean[e]*inv);
  }
  float mx = lg[0];
  #pragma unroll
  for (int e=1;e<En;e++) mx = fmaxf(mx, lg[e]);
  float pe[En]; float sum = 0.0f;
  #pragma unroll
  for (int e=0;e<En;e++){ pe[e] = expf(lg[e]-mx); sum += pe[e]; }
  #pragma unroll
  for (int e=0;e<En;e++) pe[e] /= sum;
  int i1 = 0; float p1 = pe[0];
  #pragma unroll
  for (int e=1;e<En;e++) if (pe[e] > p1){ p1 = pe[e]; i1 = e; }
  int i2 = -1; float p2 = -1.0f;
  #pragma unroll
  for (int e=0;e<En;e++) if (e != i1 && pe[e] > p2){ p2 = pe[e]; i2 = e; }
  float ws = p1 + p2;
  i1o = i1; i2o = i2; g1o = p1/ws; g2o = p2/ws;
  if (probs){
    #pragma unroll
    for (int e=0;e<En;e++) probs[e] = pe[e];
  }
}

// ============ kernel 2: persistent expert workers + aux as block 0 ============
extern __shared__ float xs[];

__global__ void __launch_bounds__(TPB, 4) k_expert(
    const float* __restrict__ x,
    const float* __restrict__ rw, const float* __restrict__ rb,
    const float* __restrict__ rg, const float* __restrict__ rbeta,
    const float* __restrict__ rmean, const float* __restrict__ rvar,
    const float* __restrict__ taus,
    const float* __restrict__ w1, const float* __restrict__ b1,
    const float* __restrict__ g1, const float* __restrict__ be1,
    const float* __restrict__ m1, const float* __restrict__ v1,
    const float* __restrict__ w2,
    float* __restrict__ out, float* __restrict__ auxout){
  int b = blockIdx.x;
  int tid = threadIdx.x, lane = tid & 31, w = tid >> 5;

  if (b == 0){
    // ---- aux block (wave 1, overlapped with workers) ----
    float* fs = xs;        // [7][8]
    float* ps = xs + 64;   // [7][8]
    float facc[En], pacc[En];
    #pragma unroll
    for (int e=0;e<En;e++){ facc[e]=0.f; pacc[e]=0.f; }
    for (int n = w; n < Nn; n += 7){
      int i1,i2; float a,bb; float pe[En];
      gate_compute(n, lane, rw, rb, rg, rbeta, rmean, rvar, i1, i2, a, bb, pe);
      #pragma unroll
      for (int e=0;e<En;e++){
        facc[e] += (i1==e || i2==e) ? 1.0f : 0.0f;
        pacc[e] += pe[e];
      }
    }
    if (lane==0){
      #pragma unroll
      for (int e=0;e<En;e++){ fs[w*8+e] = facc[e]; ps[w*8+e] = pacc[e]; }
    }
    __syncthreads();
    if (tid==0 && auxout){
      float s = 0.0f;
      #pragma unroll
      for (int e=0;e<En;e++){
        float fe = 0.f, pp = 0.f;
        #pragma unroll
        for (int q=0;q<7;q++){ fe += fs[q*8+e]; pp += ps[q*8+e]; }
        s += (fe/(float)Nn) * (pp/(float)Nn);
      }
      auxout[0] = 0.01f * (float)En * s;
    }
    return;
  }

  float* comb = xs + COMB_OFF;
  float* gsh  = xs + GATE_OFF;
  unsigned* msks = (unsigned*)(xs + MSK_OFF) + w*NR;
  int* tkt = (int*)(xs + TKT_OFF);

  for (;;){
    // ---- pull next work item (dynamic load balance; no wave quantization) ----
    if (tid == 0) *tkt = atomicAdd(&g_ticket, 1);
    __syncthreads();
    int wb = *tkt;
    if (wb >= NWORK) break;

    int n = wb / 7;
    int pbase = (wb - n*7) * PB;
    const float* xrow = x + (size_t)n*Cn*HWn + pbase;

    // ---- cooperative coalesced load of the x tile [384][28] (stride 29) ----
    for (int i = tid; i < Cn*PB; i += TPB){
      int c = i / PB, p = i - c*PB;
      xs[c*PBS + p] = xrow[(size_t)c*HWn + p];
    }

    // ---- gate once per block (warp 0), overlapped with in-flight tile loads ----
    if (w == 0){
      int e0_, e1_; float gw0_, gw1_;
      gate_compute(n, lane, rw, rb, rg, rbeta, rmean, rvar, e0_, e1_, gw0_, gw1_, (float*)0);
      if (lane == 0){
        gsh[0] = __int_as_float(e0_); gsh[1] = __int_as_float(e1_);
        gsh[2] = gw0_; gsh[3] = gw1_;
      }
    }
    __syncthreads();

    int   e0  = __float_as_int(gsh[0]), e1 = __float_as_int(gsh[1]);
    float gw0 = gsh[2], gw1 = gsh[3];

    // ---- comb[c] = gw0*a2[e0][c] + gw1*a2[e1][c] ----
    for (int c = tid; c < Cn; c += TPB)
      comb[c] = gw0*g_a2c[e0*Cn+c] + gw1*g_a2c[e1*Cn+c];

    float gws  = gw0 + gw1;
    float xm0  = g_xmin[e0], xm1 = g_xmin[e1];
    float thr0 = g_thrall[e0] - 1e-3f, thr1 = g_thrall[e1] - 1e-3f;
    float mc0  = funkey(g_maxcm_u[e0]), mc1 = funkey(g_maxcm_u[e1]);
    float tau0 = taus[e0], tau1 = taus[e1];

    __syncthreads();

    // ---- compute: warp w owns smem columns 4w..4w+3; no block barriers here ----
    for (int j=0;j<4;j++){
      int col = w*4 + j;
      float xv[NR];
      #pragma unroll
      for (int r=0;r<NR;r++) xv[r] = xs[(r*32+lane)*PBS + col];

      unsigned lmA = 0, lmB = 0;
      #pragma unroll
      for (int r=0;r<NR;r++){
        lmA |= (xv[r] >= xm0) ? (1u << r) : 0u;
        lmB |= (xv[r] >= xm1) ? (1u << r) : 0u;
      }
      #pragma unroll
      for (int r=0;r<NR;r++) xv[r] = fmaf(xv[r], gws, comb[r*32+lane]);

      int pk = __popc(lmA) | (__popc(lmB) << 16);
      int sums = __reduce_add_sync(FULLMASK, pk);
      int cntA = sums & 0xffff, cntB = sums >> 16;

      bool lightA = (float)cntA * mc0 < thr0;
      bool lightB = (float)cntB * mc1 < thr1;
      if (!(lightA && lightB)){
        #pragma unroll
        for (int k=0;k<2;k++){
          if (k ? lightB : lightA) continue;
          int   e   = k ? e1   : e0;
          float gw  = k ? gw1  : gw0;
          float tau = k ? tau1 : tau0;
          unsigned lm = k ? lmB : lmA;

          #pragma unroll
          for (int r=0;r<NR;r++){
            unsigned m = __ballot_sync(FULLMASK, (lm >> r) & 1u);
            if (lane == 0) msks[r] = m;
          }
          __syncwarp();

          // tier 2: per-group bound; lane = group g
          float ub;
          {
            const float* cmB = g_colmax32 + (size_t)e*Cn*NG + lane;
            float pr[4] = {0.f,0.f,0.f,0.f};
            #pragma unroll
            for (int r=0;r<NR;r++){
              unsigned mm = msks[r];
              float pp = 0.0f;
              while (mm){
                int bb = __ffs(mm)-1; mm &= mm-1;
                pp += cmB[(size_t)(r*32 + bb)*NG];
              }
              pr[r & 3] += pp;
            }
            ub = (pr[0]+pr[1]) + (pr[2]+pr[3]);
          }
          bool fail = ub >= g_thrmin32[e*NG + lane] - 1e-3f;
          unsigned fm = __ballot_sync(FULLMASK, fail);
          if (fm == 0) continue;

          // tier 3: exact for failing groups (rare)
          float a[NR];
          #pragma unroll
          for (int r=0;r<NR;r++) a[r] = 0.0f;
          int nf = 0;
          while (fm){
            int g = __ffs(fm)-1; fm &= fm-1;
            float h0 = 0.0f, h1 = 0.0f;
            const float* w1b  = w1 + ((size_t)e*HFn + g*GSZ)*Cn;
            const float* w1r0 = w1b + (size_t)lane*Cn;
            const float* w1r1 = w1b + (size_t)(32+lane)*Cn;
            #pragma unroll
            for (int r=0;r<NR;r++){
              unsigned mm = msks[r];
              while (mm){
                int bb = __ffs(mm)-1; mm &= mm-1;
                int c = r*32 + bb;
                h0 += w1r0[c];
                if (lane < 16) h1 += w1r1[c];
              }
            }
            int o0 = g*GSZ + lane;
            float iv0 = g1[e*HFn+o0] * rsqrtf(v1[e*HFn+o0] + 1e-5f);
            float q0  = iv0*b1[e*HFn+o0] + (be1[e*HFn+o0] - m1[e*HFn+o0]*iv0) - tau;
            bool f0 = fmaf(iv0, h0, q0) >= 0.0f;
            bool f1 = false;
            if (lane < 16){
              int o1 = g*GSZ + 32 + lane;
              float iv1 = g1[e*HFn+o1] * rsqrtf(v1[e*HFn+o1] + 1e-5f);
              float q1  = iv1*b1[e*HFn+o1] + (be1[e*HFn+o1] - m1[e*HFn+o1]*iv1) - tau;
              f1 = fmaf(iv1, h1, q1) >= 0.0f;
            }
            unsigned fa0 = __ballot_sync(FULLMASK, f0);
            unsigned fa1 = __ballot_sync(FULLMASK, f1);
            unsigned t = fa0;
            while (t){
              int bb = __ffs(t)-1; t &= t-1;
              const float* w2b = w2 + ((size_t)e*Cn + lane)*HFn + (g*GSZ + bb);
              #pragma unroll
              for (int r=0;r<NR;r++) a[r] += w2b[(size_t)r*32*HFn];
              nf++;
            }
            t = fa1;
            while (t){
              int bb = __ffs(t)-1; t &= t-1;
              const float* w2b = w2 + ((size_t)e*Cn + lane)*HFn + (g*GSZ + 32 + bb);
              #pragma unroll
              for (int r=0;r<NR;r++) a[r] += w2b[(size_t)r*32*HFn];
              nf++;
            }
          }
          if (nf){
            #pragma unroll
            for (int r=0;r<NR;r++){
              float inv2 = g_m2c[e*Cn + r*32 + lane];
              xv[r] += gw * (inv2 * a[r]);
            }
          }
        }
      }

      #pragma unroll
      for (int r=0;r<NR;r++) xs[(r*32+lane)*PBS + col] = xv[r];
    }

    __syncthreads();

    // ---- cooperative coalesced store ----
    float* orow = out + (size_t)n*Cn*HWn + pbase;
    for (int i = tid; i < Cn*PB; i += TPB){
      int c = i / PB, p = i - c*PB;
      orow[(size_t)c*HWn + p] = xs[c*PBS + p];
    }
    __syncthreads();   // smem (tile/gsh/comb) reused next iteration
  }
}

// ---------------- launch ----------------
extern "C" void kernel_launch(void* const* d_in, const int* in_sizes, int n_in,
                              void* d_out, int out_size){
  const float* x      = (const float*)d_in[0];
  const float* rw     = (const float*)d_in[1];
  const float* rb     = (const float*)d_in[2];
  const float* rgam   = (const float*)d_in[3];
  const float* rbeta  = (const float*)d_in[4];
  const float* rmean  = (const float*)d_in[5];
  const float* rvar   = (const float*)d_in[6];
  const float* w1     = (const float*)d_in[7];
  const float* b1     = (const float*)d_in[8];
  const float* g1     = (const float*)d_in[9];
  const float* be1    = (const float*)d_in[10];
  const float* m1     = (const float*)d_in[11];
  const float* v1     = (const float*)d_in[12];
  const float* w2     = (const float*)d_in[13];
  const float* b2     = (const float*)d_in[14];
  const float* g2     = (const float*)d_in[15];
  const float* be2    = (const float*)d_in[16];
  const float* m2     = (const float*)d_in[17];
  const float* v2     = (const float*)d_in[18];
  const float* taus   = (const float*)d_in[19];
  float* out = (float*)d_out;
  (void)in_sizes; (void)n_in;

  cudaFuncSetAttribute(k_expert, cudaFuncAttributeMaxDynamicSharedMemorySize, SM_BYTES);

  k_prepall<<<264 + (Bn*Cn)/8, 256>>>(x, w1, g1, be1, m1, v1, b1,
                                      g2, be2, m2, v2, b2, taus);
  float* auxp = (out_size > OUT_MAIN) ? (out + OUT_MAIN) : nullptr;
  // block 0 = aux; blocks 1..592 = persistent workers (4 per SM)
  k_expert<<<1 + 4*148, TPB, SM_BYTES>>>(x, rw, rb, rgam, rbeta, rmean, rvar,
                                         taus, w1, b1, g1, be1, m1, v1, w2,
                                         out, auxp);
}

// round 14
// speedup vs baseline: 1.2714x; 1.0423x over previous
#include <cuda_runtime.h>
#include <math.h>

#define Tn   4
#define Bn   32
#define Cn   384
#define HFn  1536
#define HWn  196
#define En   8
#define Nn   128
#define OUT_MAIN (Nn*Cn*HWn)
#define NG   32
#define GSZ  48
#define NR   12
#define FULLMASK 0xffffffffu

#define PB   28                  // pixels per worker block (7 per token)
#define PBS  29                  // smem row stride (odd -> bank-conflict-free)
#define TPB  224                 // 7 warps; each warp owns 4 pixels
#define XS_ELEMS (Cn*PBS)
#define COMB_OFF XS_ELEMS        // comb[384]
#define GATE_OFF (COMB_OFF+Cn)   // e0,e1,gw0,gw1
#define MSK_OFF  (GATE_OFF+4)    // [7][NR] unsigned
#define SM_FLOATS (MSK_OFF + 7*NR)
#define SM_BYTES  (SM_FLOATS*4)

// ---------------- device scratch ----------------
__device__ float    g_colmax32[En*Cn*NG];  // [e][c][g]
__device__ float    g_thrmin32[En*NG];
__device__ float    g_thrall[En];
__device__ unsigned g_maxcm_u[En];         // zero-init; monotone-key atomicMax (idempotent)
__device__ float    g_xmin[En];            // exact: x >= xmin  <=>  (x/tau - 1) >= 0
__device__ float    g_m2c[En*Cn];
__device__ float    g_a2c[En*Cn];
__device__ float    g_sbar[Nn*Cn];

__device__ __forceinline__ unsigned fkey(float f){
  unsigned b = __float_as_uint(f);
  return (b & 0x80000000u) ? ~b : (b | 0x80000000u);
}
__device__ __forceinline__ float funkey(unsigned k){
  unsigned b = (k & 0x80000000u) ? (k & 0x7fffffffu) : ~k;
  return __uint_as_float(b);
}

// ============ kernel 1: heterogeneous prep (colmax | thresholds | LIF) ============
__global__ void __launch_bounds__(256) k_prepall(
    const float* __restrict__ x,  const float* __restrict__ w1,
    const float* __restrict__ g1, const float* __restrict__ be1,
    const float* __restrict__ m1, const float* __restrict__ v1,
    const float* __restrict__ b1,
    const float* __restrict__ g2, const float* __restrict__ be2,
    const float* __restrict__ m2, const float* __restrict__ v2,
    const float* __restrict__ b2,
    const float* __restrict__ taus){
  int b = blockIdx.x;
  int tid = threadIdx.x, lane = tid & 31;

  if (b < 256){
    int e = b >> 5, g = b & 31;
    float lmax = -1e30f;
    for (int c = tid; c < Cn; c += 256){
      const float* base = w1 + ((size_t)e*HFn + g*GSZ)*Cn + c;
      float m = -1e30f;
      #pragma unroll 8
      for (int o=0;o<GSZ;o++) m = fmaxf(m, base[(size_t)o*Cn]);
      g_colmax32[((size_t)e*Cn + c)*NG + g] = m;
      lmax = fmaxf(lmax, m);
    }
    #pragma unroll
    for (int d=16;d>=1;d>>=1) lmax = fmaxf(lmax, __shfl_xor_sync(FULLMASK, lmax, d));
    if (lane==0) atomicMax(&g_maxcm_u[e], fkey(lmax));
    return;
  }

  if (b < 264){
    int e = b - 256;
    __shared__ float s_thr[HFn];
    float tau = taus[e];
    for (int o = tid; o < HFn; o += 256){
      float iv = g1[e*HFn+o] * rsqrtf(v1[e*HFn+o] + 1e-5f);
      float sh = be1[e*HFn+o] - m1[e*HFn+o]*iv;
      s_thr[o] = (iv > 0.0f) ? ((tau - sh)/iv - b1[e*HFn+o]) : -1e30f;
    }
    for (int c = tid; c < Cn; c += 256){
      float inv = g2[e*Cn+c] * rsqrtf(v2[e*Cn+c] + 1e-5f);
      float sh  = be2[e*Cn+c] - m2[e*Cn+c]*inv;
      g_m2c[e*Cn+c] = inv;
      g_a2c[e*Cn+c] = inv*b2[e*Cn+c] + sh;
    }
    __syncthreads();
    if (tid < NG){
      float mn = 1e30f;
      #pragma unroll 8
      for (int i=0;i<GSZ;i++) mn = fminf(mn, s_thr[tid*GSZ + i]);
      g_thrmin32[e*NG + tid] = mn;
      float ta = mn;
      #pragma unroll
      for (int d=16;d>=1;d>>=1) ta = fminf(ta, __shfl_xor_sync(FULLMASK, ta, d));
      if (tid==0) g_thrall[e] = ta;
    }
    if (tid==64){
      float y = tau;                       // tau/tau == 1 exactly
      for (int it=0; it<8; it++){
        float z = nextafterf(y, 0.0f);
        if ((z/tau - 1.0f) >= 0.0f) y = z; else break;
      }
      g_xmin[e] = y;
    }
    return;
  }

  {
    int w = (b - 264)*8 + (tid >> 5);      // 0..12287 = bidx*Cn + c
    int bi = w / Cn, c = w - bi*Cn;
    const float* xb = x + ((size_t)bi*Cn + c)*HWn;
    float v[7] = {0.f,0.f,0.f,0.f,0.f,0.f,0.f};
    #pragma unroll
    for (int t=0;t<Tn;t++){
      const float* xt = xb + (size_t)t*Bn*Cn*HWn;
      int cntl = 0;
      #pragma unroll
      for (int k=0;k<7;k++){
        int p = lane + k*32;
        if (p < HWn){
          float xv = xt[p];
          v[k] += (xv - v[k])*0.5f;
          bool s = (v[k] - 1.0f) >= 0.0f;
          cntl += s ? 1 : 0;
          if (s) v[k] = 0.0f;
        }
      }
      int cnt = __reduce_add_sync(FULLMASK, cntl);
      if (lane==0) g_sbar[(t*Bn+bi)*Cn + c] = (float)cnt / (float)HWn;
    }
  }
}

// ---------------- inline gate (identical for workers and aux) ----------------
__device__ __forceinline__ void gate_compute(
    int n, int lane,
    const float* __restrict__ rw, const float* __restrict__ rb,
    const float* __restrict__ rg, const float* __restrict__ rbeta,
    const float* __restrict__ rmean, const float* __restrict__ rvar,
    int& i1o, int& i2o, float& g1o, float& g2o, float* probs){
  float sv[NR];
  #pragma unroll
  for (int r=0;r<NR;r++) sv[r] = g_sbar[n*Cn + r*32 + lane];
  float lg[En];
  #pragma unroll
  for (int e=0;e<En;e++){
    float v = 0.0f;
    #pragma unroll
    for (int r=0;r<NR;r++) v += sv[r] * rw[e*Cn + r*32 + lane];
    #pragma unroll
    for (int d=16;d>=1;d>>=1) v += __shfl_xor_sync(FULLMASK, v, d);
    float inv = rg[e] * rsqrtf(rvar[e] + 1e-5f);
    lg[e] = inv*(v + rb[e]) + (rbeta[e] - rmean[e]*inv);
  }
  float mx = lg[0];
  #pragma unroll
  for (int e=1;e<En;e++) mx = fmaxf(mx, lg[e]);
  float pe[En]; float sum = 0.0f;
  #pragma unroll
  for (int e=0;e<En;e++){ pe[e] = expf(lg[e]-mx); sum += pe[e]; }
  #pragma unroll
  for (int e=0;e<En;e++) pe[e] /= sum;
  int i1 = 0; float p1 = pe[0];
  #pragma unroll
  for (int e=1;e<En;e++) if (pe[e] > p1){ p1 = pe[e]; i1 = e; }
  int i2 = -1; float p2 = -1.0f;
  #pragma unroll
  for (int e=0;e<En;e++) if (e != i1 && pe[e] > p2){ p2 = pe[e]; i2 = e; }
  float ws = p1 + p2;
  i1o = i1; i2o = i2; g1o = p1/ws; g2o = p2/ws;
  if (probs){
    #pragma unroll
    for (int e=0;e<En;e++) probs[e] = pe[e];
  }
}

// ============ kernel 2: expert (smem-staged, float4 tile I/O) + aux as block 0 ============
extern __shared__ float xs[];

__global__ void __launch_bounds__(TPB, 4) k_expert(
    const float* __restrict__ x,
    const float* __restrict__ rw, const float* __restrict__ rb,
    const float* __restrict__ rg, const float* __restrict__ rbeta,
    const float* __restrict__ rmean, const float* __restrict__ rvar,
    const float* __restrict__ taus,
    const float* __restrict__ w1, const float* __restrict__ b1,
    const float* __restrict__ g1, const float* __restrict__ be1,
    const float* __restrict__ m1, const float* __restrict__ v1,
    const float* __restrict__ w2,
    float* __restrict__ out, float* __restrict__ auxout){
  int b = blockIdx.x;
  int tid = threadIdx.x, lane = tid & 31, w = tid >> 5;

  if (b == 0){
    // ---- aux block (wave 1, overlapped with workers) ----
    float* fs = xs;        // [7][8]
    float* ps = xs + 64;   // [7][8]
    float facc[En], pacc[En];
    #pragma unroll
    for (int e=0;e<En;e++){ facc[e]=0.f; pacc[e]=0.f; }
    for (int n = w; n < Nn; n += 7){
      int i1,i2; float a,bb; float pe[En];
      gate_compute(n, lane, rw, rb, rg, rbeta, rmean, rvar, i1, i2, a, bb, pe);
      #pragma unroll
      for (int e=0;e<En;e++){
        facc[e] += (i1==e || i2==e) ? 1.0f : 0.0f;
        pacc[e] += pe[e];
      }
    }
    if (lane==0){
      #pragma unroll
      for (int e=0;e<En;e++){ fs[w*8+e] = facc[e]; ps[w*8+e] = pacc[e]; }
    }
    __syncthreads();
    if (tid==0 && auxout){
      float s = 0.0f;
      #pragma unroll
      for (int e=0;e<En;e++){
        float fe = 0.f, pp = 0.f;
        #pragma unroll
        for (int q=0;q<7;q++){ fe += fs[q*8+e]; pp += ps[q*8+e]; }
        s += (fe/(float)Nn) * (pp/(float)Nn);
      }
      auxout[0] = 0.01f * (float)En * s;
    }
    return;
  }

  int wb = b - 1;
  int n = wb / 7;
  int pbase = (wb - n*7) * PB;
  float* comb = xs + COMB_OFF;
  float* gsh  = xs + GATE_OFF;
  unsigned* msks = (unsigned*)(xs + MSK_OFF) + w*NR;
  const float* xrow = x + (size_t)n*Cn*HWn + pbase;   // 16B-aligned (196*4 and 28*4 are 16B multiples)

  // ---- cooperative float4 load of the x tile [384][28] (stride 29) ----
  for (int j = tid; j < (Cn*PB)/4; j += TPB){   // 2688/224 = 12 iters
    int c = j / 7, k = j - c*7;                 // 7 float4 per row
    float4 v = *(const float4*)(xrow + (size_t)c*HWn + 4*k);
    float* dst = xs + c*PBS + 4*k;
    dst[0]=v.x; dst[1]=v.y; dst[2]=v.z; dst[3]=v.w;
  }

  // ---- gate once per block (warp 0), overlapped with in-flight tile loads ----
  if (w == 0){
    int e0_, e1_; float gw0_, gw1_;
    gate_compute(n, lane, rw, rb, rg, rbeta, rmean, rvar, e0_, e1_, gw0_, gw1_, (float*)0);
    if (lane == 0){
      gsh[0] = __int_as_float(e0_); gsh[1] = __int_as_float(e1_);
      gsh[2] = gw0_; gsh[3] = gw1_;
    }
  }
  __syncthreads();

  int   e0  = __float_as_int(gsh[0]), e1 = __float_as_int(gsh[1]);
  float gw0 = gsh[2], gw1 = gsh[3];

  // ---- comb[c] = gw0*a2[e0][c] + gw1*a2[e1][c]  (covers both light contributions) ----
  for (int c = tid; c < Cn; c += TPB)
    comb[c] = gw0*g_a2c[e0*Cn+c] + gw1*g_a2c[e1*Cn+c];

  float gws  = gw0 + gw1;
  float xm0  = g_xmin[e0], xm1 = g_xmin[e1];
  float thr0 = g_thrall[e0] - 1e-3f, thr1 = g_thrall[e1] - 1e-3f;
  float mc0  = funkey(g_maxcm_u[e0]), mc1 = funkey(g_maxcm_u[e1]);
  float tau0 = taus[e0], tau1 = taus[e1];

  __syncthreads();

  // ---- compute: warp w owns smem columns 4w..4w+3; no block barriers here ----
  for (int j=0;j<4;j++){
    int col = w*4 + j;
    float xv[NR];
    #pragma unroll
    for (int r=0;r<NR;r++) xv[r] = xs[(r*32+lane)*PBS + col];

    unsigned lmA = 0, lmB = 0;
    #pragma unroll
    for (int r=0;r<NR;r++){
      lmA |= (xv[r] >= xm0) ? (1u << r) : 0u;
      lmB |= (xv[r] >= xm1) ? (1u << r) : 0u;
    }
    // residual + both experts' BN-bias terms in one pass
    #pragma unroll
    for (int r=0;r<NR;r++) xv[r] = fmaf(xv[r], gws, comb[r*32+lane]);

    int pk = __popc(lmA) | (__popc(lmB) << 16);
    int sums = __reduce_add_sync(FULLMASK, pk);
    int cntA = sums & 0xffff, cntB = sums >> 16;

    bool lightA = (float)cntA * mc0 < thr0;
    bool lightB = (float)cntB * mc1 < thr1;
    if (!(lightA && lightB)){
      #pragma unroll
      for (int k=0;k<2;k++){
        if (k ? lightB : lightA) continue;
        int   e   = k ? e1   : e0;
        float gw  = k ? gw1  : gw0;
        float tau = k ? tau1 : tau0;
        unsigned lm = k ? lmB : lmA;

        #pragma unroll
        for (int r=0;r<NR;r++){
          unsigned m = __ballot_sync(FULLMASK, (lm >> r) & 1u);
          if (lane == 0) msks[r] = m;
        }
        __syncwarp();

        // tier 2: per-group bound; lane = group g
        float ub;
        {
          const float* cmB = g_colmax32 + (size_t)e*Cn*NG + lane;
          float pr[4] = {0.f,0.f,0.f,0.f};
          #pragma unroll
          for (int r=0;r<NR;r++){
            unsigned mm = msks[r];
            float pp = 0.0f;
            while (mm){
              int bb = __ffs(mm)-1; mm &= mm-1;
              pp += cmB[(size_t)(r*32 + bb)*NG];
            }
            pr[r & 3] += pp;
          }
          ub = (pr[0]+pr[1]) + (pr[2]+pr[3]);
        }
        bool fail = ub >= g_thrmin32[e*NG + lane] - 1e-3f;
        unsigned fm = __ballot_sync(FULLMASK, fail);
        if (fm == 0) continue;                    // comb already covers this expert

        // tier 3: exact for failing groups (rare)
        float a[NR];
        #pragma unroll
        for (int r=0;r<NR;r++) a[r] = 0.0f;
        int nf = 0;
        while (fm){
          int g = __ffs(fm)-1; fm &= fm-1;
          float h0 = 0.0f, h1 = 0.0f;
          const float* w1b  = w1 + ((size_t)e*HFn + g*GSZ)*Cn;
          const float* w1r0 = w1b + (size_t)lane*Cn;
          const float* w1r1 = w1b + (size_t)(32+lane)*Cn;
          #pragma unroll
          for (int r=0;r<NR;r++){
            unsigned mm = msks[r];
            while (mm){
              int bb = __ffs(mm)-1; mm &= mm-1;
              int c = r*32 + bb;
              h0 += w1r0[c];
              if (lane < 16) h1 += w1r1[c];
            }
          }
          int o0 = g*GSZ + lane;
          float iv0 = g1[e*HFn+o0] * rsqrtf(v1[e*HFn+o0] + 1e-5f);
          float q0  = iv0*b1[e*HFn+o0] + (be1[e*HFn+o0] - m1[e*HFn+o0]*iv0) - tau;
          bool f0 = fmaf(iv0, h0, q0) >= 0.0f;
          bool f1 = false;
          if (lane < 16){
            int o1 = g*GSZ + 32 + lane;
            float iv1 = g1[e*HFn+o1] * rsqrtf(v1[e*HFn+o1] + 1e-5f);
            float q1  = iv1*b1[e*HFn+o1] + (be1[e*HFn+o1] - m1[e*HFn+o1]*iv1) - tau;
            f1 = fmaf(iv1, h1, q1) >= 0.0f;
          }
          unsigned fa0 = __ballot_sync(FULLMASK, f0);
          unsigned fa1 = __ballot_sync(FULLMASK, f1);
          unsigned t = fa0;
          while (t){
            int bb = __ffs(t)-1; t &= t-1;
            const float* w2b = w2 + ((size_t)e*Cn + lane)*HFn + (g*GSZ + bb);
            #pragma unroll
            for (int r=0;r<NR;r++) a[r] += w2b[(size_t)r*32*HFn];
            nf++;
          }
          t = fa1;
          while (t){
            int bb = __ffs(t)-1; t &= t-1;
            const float* w2b = w2 + ((size_t)e*Cn + lane)*HFn + (g*GSZ + 32 + bb);
            #pragma unroll
            for (int r=0;r<NR;r++) a[r] += w2b[(size_t)r*32*HFn];
            nf++;
          }
        }
        if (nf){
          // comb carries gw*a2; heavy correction is gw*inv2*a only
          #pragma unroll
          for (int r=0;r<NR;r++){
            float inv2 = g_m2c[e*Cn + r*32 + lane];
            xv[r] += gw * (inv2 * a[r]);
          }
        }
      }
    }

    #pragma unroll
    for (int r=0;r<NR;r++) xs[(r*32+lane)*PBS + col] = xv[r];
  }

  __syncthreads();

  // ---- cooperative float4 store ----
  float* orow = out + (size_t)n*Cn*HWn + pbase;
  for (int j = tid; j < (Cn*PB)/4; j += TPB){
    int c = j / 7, k = j - c*7;
    const float* src = xs + c*PBS + 4*k;
    float4 v = make_float4(src[0], src[1], src[2], src[3]);
    *(float4*)(orow + (size_t)c*HWn + 4*k) = v;
  }
}

// ---------------- launch ----------------
extern "C" void kernel_launch(void* const* d_in, const int* in_sizes, int n_in,
                              void* d_out, int out_size){
  const float* x      = (const float*)d_in[0];
  const float* rw     = (const float*)d_in[1];
  const float* rb     = (const float*)d_in[2];
  const float* rgam   = (const float*)d_in[3];
  const float* rbeta  = (const float*)d_in[4];
  const float* rmean  = (const float*)d_in[5];
  const float* rvar   = (const float*)d_in[6];
  const float* w1     = (const float*)d_in[7];
  const float* b1     = (const float*)d_in[8];
  const float* g1     = (const float*)d_in[9];
  const float* be1    = (const float*)d_in[10];
  const float* m1     = (const float*)d_in[11];
  const float* v1     = (const float*)d_in[12];
  const float* w2     = (const float*)d_in[13];
  const float* b2     = (const float*)d_in[14];
  const float* g2     = (const float*)d_in[15];
  const float* be2    = (const float*)d_in[16];
  const float* m2     = (const float*)d_in[17];
  const float* v2     = (const float*)d_in[18];
  const float* taus   = (const float*)d_in[19];
  float* out = (float*)d_out;
  (void)in_sizes; (void)n_in;

  cudaFuncSetAttribute(k_expert, cudaFuncAttributeMaxDynamicSharedMemorySize, SM_BYTES);

  k_prepall<<<264 + (Bn*Cn)/8, 256>>>(x, w1, g1, be1, m1, v1, b1,
                                      g2, be2, m2, v2, b2, taus);
  float* auxp = (out_size > OUT_MAIN) ? (out + OUT_MAIN) : nullptr;
  // block 0 = aux; blocks 1..896 = workers (7 per token), static grid
  k_expert<<<1 + Nn*7, TPB, SM_BYTES>>>(x, rw, rb, rgam, rbeta, rmean, rvar,
                                        taus, w1, b1, g1, be1, m1, v1, w2,
                                        out, auxp);
}